// round 17
// baseline (speedup 1.0000x reference)
#include <cuda_runtime.h>
#include <cstdint>

#define BATCH   512
#define NCTX    1000
#define DIM     128
#define NHEADS  8
#define HDIM    16
#define HTOT    128
#define CATD    384
#define BPREP   8
#define NPW     125            // tokens per warp (1000/8 exact)
#define RSTRIDE 36             // transpose-reduce row stride (bank-conflict-free)

// Folded query vectors u[b][h][d] (Wk folded into q, 1/16 folded in)
__device__ float g_U[BATCH * NHEADS * DIM];

// ---------------------------------------------------------------------------
// Prep (batched): 8 batches per CTA.
// ---------------------------------------------------------------------------
__global__ __launch_bounds__(128)
void prep_kernel(const float* __restrict__ state,
                 const float* __restrict__ Wq,
                 const float* __restrict__ Wk) {
    __shared__ float st[BPREP][CATD];
    __shared__ float qs[BPREP][HTOT];
    int b0 = blockIdx.x * BPREP, t = threadIdx.x;

    for (int i = t; i < BPREP * CATD / 4; i += 128)
        ((float4*)&st[0][0])[i] = ((const float4*)(state + (size_t)b0 * CATD))[i];
    __syncthreads();

    {
        const float4* wr = (const float4*)(Wq + (size_t)t * CATD);
        float acc[BPREP];
        #pragma unroll
        for (int b = 0; b < BPREP; b++) acc[b] = 0.f;
        for (int j = 0; j < CATD / 4; j++) {
            float4 w = wr[j];
            #pragma unroll
            for (int b = 0; b < BPREP; b++) {
                float4 s = ((const float4*)st[b])[j];
                acc[b] += w.x*s.x + w.y*s.y + w.z*s.z + w.w*s.w;
            }
        }
        #pragma unroll
        for (int b = 0; b < BPREP; b++) qs[b][t] = acc[b];
    }
    __syncthreads();

    for (int h = 0; h < NHEADS; h++) {
        float wk[HDIM];
        #pragma unroll
        for (int j = 0; j < HDIM; j++)
            wk[j] = Wk[(size_t)(h * HDIM + j) * DIM + t];
        #pragma unroll
        for (int b = 0; b < BPREP; b++) {
            float acc = 0.f;
            #pragma unroll
            for (int j = 0; j < HDIM; j++) acc += qs[b][h * HDIM + j] * wk[j];
            g_U[(size_t)(b0 + b) * (NHEADS * DIM) + h * DIM + t] = acc * 0.0625f;
        }
    }
}

// ---------------------------------------------------------------------------
// Warp-autonomous fused kernel: no main-loop __syncthreads, x read once,
// u register-resident. Lane owns dims [lane*4, lane*4+4); warp = full token.
// ---------------------------------------------------------------------------
__global__ __launch_bounds__(256)
void attn_kernel(const float* __restrict__ context,
                 const void* __restrict__ mask_raw,   // uint8 / int32 / fp32 bool
                 const float* __restrict__ Wv,
                 const float* __restrict__ Wfc,
                 float* __restrict__ out) {
    __shared__ float scratch[8 * 1024];   // per-warp red area; then c-reduce
    __shared__ float l_s[NHEADS];
    __shared__ float o_s[HTOT];

    const int b = blockIdx.x, t = threadIdx.x;
    const int wid = t >> 5, lane = t & 31;

    // mask-encoding discriminator
    const unsigned int*  mw  = (const unsigned int*)mask_raw;
    const unsigned char* mb8 = (const unsigned char*)mask_raw;
    if (t < NHEADS) l_s[t] = 0.f;
    unsigned int wsamp = mw[t];
    bool okw = (wsamp == 0u) || (wsamp == 1u) || (wsamp == 0x3F800000u);
    const bool word_enc = __syncthreads_and((int)okw);   // also orders l_s init

    // u[h][j] for this lane's dims — registers, loaded once
    float u[NHEADS][4];
    {
        const float* Ub = g_U + (size_t)b * (NHEADS * DIM) + lane * 4;
        #pragma unroll
        for (int h = 0; h < NHEADS; h++) {
            float4 uv = *(const float4*)(Ub + h * DIM);
            u[h][0] = uv.x; u[h][1] = uv.y; u[h][2] = uv.z; u[h][3] = uv.w;
        }
    }

    float c[NHEADS][4];
    #pragma unroll
    for (int h = 0; h < NHEADS; h++)
        c[h][0] = c[h][1] = c[h][2] = c[h][3] = 0.f;
    float l_own = 0.f;                     // accumulates e of head (lane&7)

    float* red = scratch + wid * 1024;     // [2][NHEADS][RSTRIDE] (576 used)
    const int h8 = lane & 7, seg = lane >> 3;

    const float* ctx_b = context + (size_t)b * NCTX * DIM;
    const unsigned int*  mwb  = mw  + (size_t)b * NCTX;
    const unsigned char* mb8b = mb8 + (size_t)b * NCTX;

    const int n_begin = wid * NPW, n_end = n_begin + NPW;

    // depth-1 prefetch
    float4 xc = *(const float4*)(ctx_b + (size_t)n_begin * DIM + lane * 4);
    int mc = word_enc ? (mwb[n_begin] != 0u) : (mb8b[n_begin] != 0);

    #pragma unroll 2
    for (int n = n_begin; n < n_end; n++) {
        float4 x = xc; int m = mc;
        int n1 = n + 1;
        if (n1 < n_end) {
            xc = *(const float4*)(ctx_b + (size_t)n1 * DIM + lane * 4);
            mc = word_enc ? (mwb[n1] != 0u) : (mb8b[n1] != 0);
        }

        // partial dots (8 independent chains)
        float p[NHEADS];
        #pragma unroll
        for (int h = 0; h < NHEADS; h++)
            p[h] = u[h][0]*x.x + u[h][1]*x.y + u[h][2]*x.z + u[h][3]*x.w;

        // transpose-reduce via smem (parity double buffer, 1 syncwarp/token)
        float* rp = red + (n & 1) * (NHEADS * RSTRIDE);
        #pragma unroll
        for (int h = 0; h < NHEADS; h++)
            rp[h * RSTRIDE + lane] = p[h];
        __syncwarp();
        const float4* g4 = (const float4*)(rp + h8 * RSTRIDE + seg * 8);
        float4 a0 = g4[0], a1 = g4[1];
        float s = ((a0.x + a0.y) + (a0.z + a0.w))
                + ((a1.x + a1.y) + (a1.z + a1.w));
        s += __shfl_xor_sync(0xffffffffu, s, 8);
        s += __shfl_xor_sync(0xffffffffu, s, 16);

        float e = m ? 0.f : __expf(s);     // lane's head = h8
        l_own += e;

        float eb[NHEADS];
        #pragma unroll
        for (int h = 0; h < NHEADS; h++)
            eb[h] = __shfl_sync(0xffffffffu, e, h);   // lane h holds head h

        #pragma unroll
        for (int h = 0; h < NHEADS; h++) {
            c[h][0] += eb[h] * x.x;
            c[h][1] += eb[h] * x.y;
            c[h][2] += eb[h] * x.z;
            c[h][3] += eb[h] * x.w;
        }
    }

    // l: 4 replica lanes per head hold identical sums; lane<8 contributes
    if (lane < NHEADS) atomicAdd(&l_s[lane], l_own);

    // c partials: each warp stores its [8][128] block, then block-reduce
    __syncthreads();   // main loop + atomics done; red area reusable
    {
        float* reg = scratch + wid * 1024;
        #pragma unroll
        for (int h = 0; h < NHEADS; h++)
            *(float4*)(reg + h * DIM + lane * 4) =
                make_float4(c[h][0], c[h][1], c[h][2], c[h][3]);
    }
    __syncthreads();
    for (int i = t; i < NHEADS * DIM; i += 256) {
        float s = scratch[i];
        #pragma unroll
        for (int w = 1; w < 8; w++) s += scratch[w * 1024 + i];
        scratch[i] = s;   // only this thread touches scratch[i] (w=0 term)
    }
    __syncthreads();

    // o[t] = <Wv[t,:], c_h>/l_h  (head-concat order), then y = Wfc @ o
    if (t < HTOT) {
        int h = t >> 4;
        const float4* wv = (const float4*)(Wv + (size_t)t * DIM);
        const float4* cf = (const float4*)(scratch + h * DIM);
        float acc = 0.f;
        #pragma unroll
        for (int k = 0; k < DIM / 4; k++) {
            float4 w = wv[k], cc4 = cf[k];
            acc += w.x*cc4.x + w.y*cc4.y + w.z*cc4.z + w.w*cc4.w;
        }
        o_s[t] = acc / l_s[h];
    }
    __syncthreads();
    if (t < HTOT) {
        const float4* wf = (const float4*)(Wfc + (size_t)t * DIM);
        const float4* oo = (const float4*)o_s;
        float acc = 0.f;
        #pragma unroll
        for (int k = 0; k < DIM / 4; k++) {
            float4 w = wf[k], o4 = oo[k];
            acc += w.x*o4.x + w.y*o4.y + w.z*o4.z + w.w*o4.w;
        }
        out[(size_t)b * HTOT + t] = acc;
    }
}

// ---------------------------------------------------------------------------
extern "C" void kernel_launch(void* const* d_in, const int* in_sizes, int n_in,
                              void* d_out, int out_size) {
    const float* state   = (const float*)d_in[0];
    const float* context = (const float*)d_in[1];
    const void*  mask    = d_in[2];
    const float* Wq      = (const float*)d_in[3];
    const float* Wk      = (const float*)d_in[4];
    const float* Wv      = (const float*)d_in[5];
    const float* Wfc     = (const float*)d_in[6];
    float*       out     = (float*)d_out;

    prep_kernel<<<BATCH / BPREP, 128>>>(state, Wq, Wk);
    attn_kernel<<<BATCH, 256>>>(context, mask, Wv, Wfc, out);
}